// round 4
// baseline (speedup 1.0000x reference)
#include <cuda_runtime.h>

// Problem constants
#define NS   65536
#define KEXP 8
#define DIN  74
#define WID  64
#define DOUT 32
#define TILE 256
#define NT   256
#define MAXTILES (NS / TILE + KEXP)
#define NSCAT 256

// smem (floats)
#define XS_F (DIN * TILE)     // 18944
#define HS_F (WID * TILE)     // 16384
#define W0D_F (DIN * 128)     // 9472   (dup'd 64->128)
#define W1D_F (WID * 128)     // 8192
#define W2D_F (WID * 64)      // 4096   (dup'd 32->64)
#define B_F  (WID + WID + DOUT)
#define SMEM_BYTES ((XS_F + HS_F + W0D_F + W1D_F + W2D_F + B_F) * 4 + TILE * 4)

typedef unsigned long long u64;

// ---------------- device scratch ----------------
__device__ int g_hist[KEXP];           // zero-init at load; k_scan re-zeroes after use
__device__ int g_offs[KEXP + 1];
__device__ int g_cursor[KEXP];
__device__ int g_order[NS];

// ---------------- packed fp32x2 helpers ----------------
__device__ __forceinline__ u64 pk2(float x, float y) {
    u64 r; asm("mov.b64 %0, {%1, %2};" : "=l"(r) : "f"(x), "f"(y)); return r;
}
__device__ __forceinline__ void upk2(u64 p, float& x, float& y) {
    asm("mov.b64 {%0, %1}, %2;" : "=f"(x), "=f"(y) : "l"(p));
}
__device__ __forceinline__ void fma2(u64& c, u64 a, u64 b) {
    asm("fma.rn.f32x2 %0, %1, %2, %0;" : "+l"(c) : "l"(a), "l"(b));
}

// ---------------- bucketing ----------------
__global__ void k_hist(const int* __restrict__ idxs) {
    __shared__ int sh[KEXP];
    if (threadIdx.x < KEXP) sh[threadIdx.x] = 0;
    __syncthreads();
    atomicAdd(&sh[idxs[blockIdx.x * 256 + threadIdx.x]], 1);
    __syncthreads();
    if (threadIdx.x < KEXP) atomicAdd(&g_hist[threadIdx.x], sh[threadIdx.x]);
}

__global__ void k_scan() {
    int acc = 0;
    for (int e = 0; e < KEXP; e++) {
        g_offs[e] = acc; g_cursor[e] = acc;
        acc += g_hist[e];
        g_hist[e] = 0;
    }
    g_offs[KEXP] = acc;
}

__global__ void k_scatter(const int* __restrict__ idxs) {
    __shared__ int s_loc[KEXP];
    __shared__ int s_base[KEXP];
    if (threadIdx.x < KEXP) s_loc[threadIdx.x] = 0;
    __syncthreads();
    int i = blockIdx.x * 256 + threadIdx.x;
    int e = idxs[i];
    int r = atomicAdd(&s_loc[e], 1);
    __syncthreads();
    if (threadIdx.x < KEXP)
        s_base[threadIdx.x] = atomicAdd(&g_cursor[threadIdx.x], s_loc[threadIdx.x]);
    __syncthreads();
    g_order[s_base[e] + r] = i;
}

// ---------------- weight staging ----------------
// duplicated copy: src [KD][C] -> dst [KD][2C], dst[k][2c]=dst[k][2c+1]=src[k][c]
template <int C>
__device__ __forceinline__ void copy_dup(float* __restrict__ dst, const float* __restrict__ src,
                                         int n, int tid) {
    for (int i = tid; i < n; i += NT) {
        float v = src[i];
        int k = i / C, c = i % C;
        *(float2*)&dst[k * (2 * C) + 2 * c] = make_float2(v, v);
    }
}

// ---------------- operand loaders (register double-buffer) ----------------
__device__ __forceinline__ void lod16(const float* __restrict__ A, const float* __restrict__ Wd,
                                      int k, int s0, int c0, ulonglong2& av, u64* b) {
    av = *(const ulonglong2*)&A[k * TILE + s0];                 // LDS.128, conflict-free
    const ulonglong2* wp = (const ulonglong2*)&Wd[k * 128 + 2 * c0];  // broadcast
#pragma unroll
    for (int j = 0; j < 8; j++) { ulonglong2 t = wp[j]; b[2 * j] = t.x; b[2 * j + 1] = t.y; }
}
__device__ __forceinline__ void lod8(const float* __restrict__ A, const float* __restrict__ Wd,
                                     int k, int s0, int c0, ulonglong2& av, u64* b) {
    av = *(const ulonglong2*)&A[k * TILE + s0];
    const ulonglong2* wp = (const ulonglong2*)&Wd[k * 64 + 2 * c0];
#pragma unroll
    for (int j = 0; j < 4; j++) { ulonglong2 t = wp[j]; b[2 * j] = t.x; b[2 * j + 1] = t.y; }
}

// ---------------- GEMM: [256 x KD] @ [KD x 64] + bias, relu -> O[64][256] ----------------
// Thread: 4 contiguous samples x 16 cols. KD must be even.
template <int KD>
__device__ __forceinline__ void gemm_relu(const float* __restrict__ A,
                                          const float* __restrict__ Wd,   // [KD][128] dup'd
                                          const float* __restrict__ bias,
                                          float* __restrict__ O,
                                          int s0, int c0) {
    u64 acc0[16], acc1[16];
#pragma unroll
    for (int j = 0; j < 16; j++) {
        float bv = bias[c0 + j];
        u64 b = pk2(bv, bv);
        acc0[j] = b; acc1[j] = b;
    }
    ulonglong2 av0, av1;
    u64 b0[16], b1[16];
    lod16(A, Wd, 0, s0, c0, av0, b0);
#pragma unroll 1
    for (int k = 0; k < KD; k += 2) {
        lod16(A, Wd, k + 1, s0, c0, av1, b1);
#pragma unroll
        for (int j = 0; j < 16; j++) { fma2(acc0[j], av0.x, b0[j]); fma2(acc1[j], av0.y, b0[j]); }
        if (k + 2 < KD) lod16(A, Wd, k + 2, s0, c0, av0, b0);
#pragma unroll
        for (int j = 0; j < 16; j++) { fma2(acc0[j], av1.x, b1[j]); fma2(acc1[j], av1.y, b1[j]); }
    }
#pragma unroll
    for (int j = 0; j < 16; j++) {
        float x0, x1, x2, x3;
        upk2(acc0[j], x0, x1);
        upk2(acc1[j], x2, x3);
        *(float4*)&O[(c0 + j) * TILE + s0] =
            make_float4(fmaxf(x0, 0.f), fmaxf(x1, 0.f), fmaxf(x2, 0.f), fmaxf(x3, 0.f));
    }
}

// ---------------- final layer: [256 x 64] @ [64 x 32] + bias -> global scatter ----------------
// Thread: 4 contiguous samples x 8 cols.
__device__ __forceinline__ void gemm_out(const float* __restrict__ A,
                                         const float* __restrict__ Wd,   // [64][64] dup'd
                                         const float* __restrict__ bias, float* __restrict__ out,
                                         const int* __restrict__ sids, int cnt, int s0, int c0) {
    u64 acc0[8], acc1[8];
#pragma unroll
    for (int j = 0; j < 8; j++) {
        float bv = bias[c0 + j];
        u64 b = pk2(bv, bv);
        acc0[j] = b; acc1[j] = b;
    }
    ulonglong2 av0, av1;
    u64 b0[8], b1[8];
    lod8(A, Wd, 0, s0, c0, av0, b0);
#pragma unroll 1
    for (int k = 0; k < WID; k += 2) {
        lod8(A, Wd, k + 1, s0, c0, av1, b1);
#pragma unroll
        for (int j = 0; j < 8; j++) { fma2(acc0[j], av0.x, b0[j]); fma2(acc1[j], av0.y, b0[j]); }
        if (k + 2 < WID) lod8(A, Wd, k + 2, s0, c0, av0, b0);
#pragma unroll
        for (int j = 0; j < 8; j++) { fma2(acc0[j], av1.x, b1[j]); fma2(acc1[j], av1.y, b1[j]); }
    }
    // acc0: samples s0, s0+1 ; acc1: samples s0+2, s0+3 (per j: lo/hi)
    float r[4][8];
#pragma unroll
    for (int j = 0; j < 8; j++) {
        upk2(acc0[j], r[0][j], r[1][j]);
        upk2(acc1[j], r[2][j], r[3][j]);
    }
#pragma unroll
    for (int p = 0; p < 4; p++) {
        if (s0 + p < cnt) {
            float* dst = &out[(size_t)sids[s0 + p] * DOUT + c0];
            *(float4*)dst       = make_float4(r[p][0], r[p][1], r[p][2], r[p][3]);
            *(float4*)(dst + 4) = make_float4(r[p][4], r[p][5], r[p][6], r[p][7]);
        }
    }
}

// ---------------- fused MLP kernel ----------------
__global__ void __launch_bounds__(NT, 1) k_mlp(
    const float* __restrict__ positions, const float* __restrict__ viewdirs,
    const float* __restrict__ features,
    const float* __restrict__ W0, const float* __restrict__ b0,
    const float* __restrict__ W1, const float* __restrict__ b1,
    const float* __restrict__ W2, const float* __restrict__ b2,
    float* __restrict__ out) {
    extern __shared__ float sm[];
    float* Xs  = sm;                        // [74][256], reused as layer-1 output
    float* Hs  = Xs + XS_F;                 // [64][256]
    float* W0d = Hs + HS_F;                 // [74][128] dup
    float* W1d = W0d + W0D_F;               // [64][128] dup
    float* W2d = W1d + W1D_F;               // [64][64]  dup
    float* B0  = W2d + W2D_F;
    float* B1  = B0 + WID;
    float* B2  = B1 + WID;
    int* sids  = (int*)(B2 + DOUT);
    int tid = threadIdx.x;

    // blockIdx -> (expert, local tile)
    int e = -1, lt = 0;
    {
        int b = blockIdx.x, acc = 0;
#pragma unroll
        for (int i = 0; i < KEXP; i++) {
            int tiles = (g_offs[i + 1] - g_offs[i] + TILE - 1) / TILE;
            if (e < 0 && b < acc + tiles) { e = i; lt = b - acc; }
            acc += tiles;
        }
    }
    if (e < 0) return;
    int base = g_offs[e] + lt * TILE;
    int cnt = min(TILE, g_offs[e + 1] - base);

    // ---- stage weights (dup'd) ----
    copy_dup<WID>(W0d, W0 + e * DIN * WID, DIN * WID, tid);
    copy_dup<WID>(W1d, W1 + e * WID * WID, WID * WID, tid);
    copy_dup<DOUT>(W2d, W2 + e * WID * DOUT, WID * DOUT, tid);
    if (tid < WID) { B0[tid] = b0[e * WID + tid]; B1[tid] = b1[e * WID + tid]; }
    else if (tid < WID + DOUT) B2[tid - WID] = b2[e * DOUT + tid - WID];

    // ---- gather + encode (one sample per thread) ----
    {
        int n = g_order[base + min(tid, cnt - 1)];   // pad partial tiles with a valid row
        sids[tid] = n;
        const float4* f4 = (const float4*)(features + (size_t)n * 32);
#pragma unroll
        for (int i = 0; i < 8; i++) {
            float4 f = f4[i];
            Xs[(i * 4 + 0) * TILE + tid] = f.x;
            Xs[(i * 4 + 1) * TILE + tid] = f.y;
            Xs[(i * 4 + 2) * TILE + tid] = f.z;
            Xs[(i * 4 + 3) * TILE + tid] = f.w;
        }
        float p0 = positions[n * 3], p1 = positions[n * 3 + 1], p2 = positions[n * 3 + 2];
        Xs[32 * TILE + tid] = p0; Xs[33 * TILE + tid] = p1; Xs[34 * TILE + tid] = p2;
#pragma unroll
        for (int s = 0; s < 2; s++) {
            float sc = (float)(1 << s);
            float v0 = p0 * sc, v1 = p1 * sc, v2 = p2 * sc;
            Xs[(35 + s * 3) * TILE + tid] = __sinf(v0);
            Xs[(36 + s * 3) * TILE + tid] = __sinf(v1);
            Xs[(37 + s * 3) * TILE + tid] = __sinf(v2);
            Xs[(41 + s * 3) * TILE + tid] = __cosf(v0);
            Xs[(42 + s * 3) * TILE + tid] = __cosf(v1);
            Xs[(43 + s * 3) * TILE + tid] = __cosf(v2);
        }
        float q0 = viewdirs[n * 3], q1 = viewdirs[n * 3 + 1], q2 = viewdirs[n * 3 + 2];
        Xs[47 * TILE + tid] = q0; Xs[48 * TILE + tid] = q1; Xs[49 * TILE + tid] = q2;
#pragma unroll
        for (int s = 0; s < 4; s++) {
            float sc = (float)(1 << s);
            float v0 = q0 * sc, v1 = q1 * sc, v2 = q2 * sc;
            Xs[(50 + s * 3) * TILE + tid] = __sinf(v0);
            Xs[(51 + s * 3) * TILE + tid] = __sinf(v1);
            Xs[(52 + s * 3) * TILE + tid] = __sinf(v2);
            Xs[(62 + s * 3) * TILE + tid] = __cosf(v0);
            Xs[(63 + s * 3) * TILE + tid] = __cosf(v1);
            Xs[(64 + s * 3) * TILE + tid] = __cosf(v2);
        }
    }
    __syncthreads();

    // thread tile: warp w (0..7): cols (w&3)*16, samples ((w>>2)*32 + lane)*4
    int lane = tid & 31;
    int w = tid >> 5;
    int c0 = (w & 3) * 16;
    int s0 = ((w >> 2) * 32 + lane) * 4;

    gemm_relu<DIN>(Xs, W0d, B0, Hs, s0, c0);
    __syncthreads();
    gemm_relu<WID>(Hs, W1d, B1, Xs, s0, c0);
    __syncthreads();

    int c0o = (w & 3) * 8;   // 4 groups x 8 cols = 32
    gemm_out(Xs, W2d, B2, out, sids, cnt, s0, c0o);
}

// ---------------- launch ----------------
extern "C" void kernel_launch(void* const* d_in, const int* in_sizes, int n_in,
                              void* d_out, int out_size) {
    (void)in_sizes; (void)n_in; (void)out_size;
    const int*   idxs      = (const int*)d_in[0];
    const float* positions = (const float*)d_in[1];
    const float* viewdirs  = (const float*)d_in[2];
    const float* features  = (const float*)d_in[3];
    const float* W0 = (const float*)d_in[4];
    const float* b0 = (const float*)d_in[5];
    const float* W1 = (const float*)d_in[6];
    const float* b1 = (const float*)d_in[7];
    const float* W2 = (const float*)d_in[8];
    const float* b2 = (const float*)d_in[9];
    float* out = (float*)d_out;

    cudaFuncSetAttribute(k_mlp, cudaFuncAttributeMaxDynamicSharedMemorySize, SMEM_BYTES);

    k_hist<<<NSCAT, 256>>>(idxs);
    k_scan<<<1, 1>>>();
    k_scatter<<<NSCAT, 256>>>(idxs);
    k_mlp<<<MAXTILES, NT, SMEM_BYTES>>>(positions, viewdirs, features,
                                        W0, b0, W1, b1, W2, b2, out);
}

// round 6
// speedup vs baseline: 1.5560x; 1.5560x over previous
#include <cuda_runtime.h>
#include <cuda_bf16.h>

typedef unsigned int u32;

// ---------------- problem constants ----------------
#define NS    65536
#define KEXP  8
#define DIN   74
#define WID   64
#define DOUT  32
#define TILE  128
#define NT    256
#define MAXTILES (NS / TILE + KEXP)
#define NSCAT 256

// ---------------- smem layout (bytes) ----------------
#define SM_XH0  0                 // A/H hi panel0: [128 rows][128B] (k 0..63)
#define SM_XL0  16384             // A/H lo panel0
#define SM_XH1  32768             // A hi panel1: [128 rows][48B stride] (k 64..79)
#define SM_XL1  38912
#define SM_W0H0 45056             // W0^T hi p0: [64 n][128B]
#define SM_W0H1 53248             // W0^T hi p1: [64 n][48B]
#define SM_W0L0 56320
#define SM_W0L1 64512
#define SM_W1H  67584             // W1^T hi: [64 n][128B]
#define SM_W1L  75776
#define SM_GH   45056             // layer-2 input overlays dead W0/W1 region
#define SM_GL   61440
#define SM_W2H  83968             // W2^T hi: [32 n][128B]
#define SM_W2L  88064
#define SM_B0   92160
#define SM_B1   92416
#define SM_B2   92672
#define SM_SIDS 92800
#define SMEM_BYTES (SM_SIDS + TILE * 4)   // 93312

#define SWZ(off) ((off) ^ (((off) >> 3) & 0x70))

// ---------------- device scratch ----------------
__device__ int g_hist[KEXP];
__device__ int g_offs[KEXP + 1];
__device__ int g_cursor[KEXP];
__device__ int g_order[NS];

// ---------------- bucketing ----------------
__global__ void k_hist(const int* __restrict__ idxs) {
    __shared__ int sh[KEXP];
    if (threadIdx.x < KEXP) sh[threadIdx.x] = 0;
    __syncthreads();
    atomicAdd(&sh[idxs[blockIdx.x * 256 + threadIdx.x]], 1);
    __syncthreads();
    if (threadIdx.x < KEXP) atomicAdd(&g_hist[threadIdx.x], sh[threadIdx.x]);
}
__global__ void k_scan() {
    int acc = 0;
    for (int e = 0; e < KEXP; e++) {
        g_offs[e] = acc; g_cursor[e] = acc;
        acc += g_hist[e];
        g_hist[e] = 0;
    }
    g_offs[KEXP] = acc;
}
__global__ void k_scatter(const int* __restrict__ idxs) {
    __shared__ int s_loc[KEXP];
    __shared__ int s_base[KEXP];
    if (threadIdx.x < KEXP) s_loc[threadIdx.x] = 0;
    __syncthreads();
    int i = blockIdx.x * 256 + threadIdx.x;
    int e = idxs[i];
    int r = atomicAdd(&s_loc[e], 1);
    __syncthreads();
    if (threadIdx.x < KEXP)
        s_base[threadIdx.x] = atomicAdd(&g_cursor[threadIdx.x], s_loc[threadIdx.x]);
    __syncthreads();
    g_order[s_base[e] + r] = i;
}

// ---------------- PTX helpers (baseline ISA only; no arch-accel features) ----------------
__device__ __forceinline__ u32 smem_u32(const void* p) {
    u32 a; asm("{ .reg .u64 t; cvta.to.shared.u64 t, %1; cvt.u32.u64 %0, t; }" : "=r"(a) : "l"(p));
    return a;
}
__device__ __forceinline__ void ldmA(u32 a[4], u32 addr) {
    asm volatile("ldmatrix.sync.aligned.m8n8.x4.shared.b16 {%0,%1,%2,%3}, [%4];"
                 : "=r"(a[0]), "=r"(a[1]), "=r"(a[2]), "=r"(a[3]) : "r"(addr));
}
__device__ __forceinline__ void ldmB(u32 b[2], u32 addr) {
    asm volatile("ldmatrix.sync.aligned.m8n8.x2.shared.b16 {%0,%1}, [%2];"
                 : "=r"(b[0]), "=r"(b[1]) : "r"(addr));
}
__device__ __forceinline__ void mma16816(float c[4], const u32 a[4], const u32 b[2]) {
    asm volatile(
        "mma.sync.aligned.m16n8k16.row.col.f32.bf16.bf16.f32 "
        "{%0,%1,%2,%3}, {%4,%5,%6,%7}, {%8,%9}, {%0,%1,%2,%3};"
        : "+f"(c[0]), "+f"(c[1]), "+f"(c[2]), "+f"(c[3])
        : "r"(a[0]), "r"(a[1]), "r"(a[2]), "r"(a[3]), "r"(b[0]), "r"(b[1]));
}

__device__ __forceinline__ u32 bpack(__nv_bfloat16 a, __nv_bfloat16 b) {
    __nv_bfloat162 t(a, b);
    return *reinterpret_cast<u32*>(&t);
}
// split (v0,v1) into hi/lo bf16 pairs; store u32 each at given smem byte offsets
__device__ __forceinline__ void store_split(char* sm, u32 offH, u32 offL, float v0, float v1) {
    __nv_bfloat16 h0 = __float2bfloat16(v0), h1 = __float2bfloat16(v1);
    float l0 = v0 - __bfloat162float(h0), l1 = v1 - __bfloat162float(h1);
    *(u32*)(sm + offH) = bpack(h0, h1);
    *(u32*)(sm + offL) = bpack(__float2bfloat16(l0), __float2bfloat16(l1));
}

// ---------------- fused MMA MLP kernel ----------------
__global__ void __launch_bounds__(NT, 2) k_mlp(
    const float* __restrict__ positions, const float* __restrict__ viewdirs,
    const float* __restrict__ features,
    const float* __restrict__ W0g, const float* __restrict__ b0g,
    const float* __restrict__ W1g, const float* __restrict__ b1g,
    const float* __restrict__ W2g, const float* __restrict__ b2g,
    float* __restrict__ out) {
    extern __shared__ char sm[];
    const u32 smb = smem_u32(sm);
    const int tid = threadIdx.x, lane = tid & 31, wid = tid >> 5;

    // blockIdx -> (expert, local tile)
    int e = -1, lt = 0;
    {
        int b = blockIdx.x, acc = 0;
#pragma unroll
        for (int i = 0; i < KEXP; i++) {
            int tiles = (g_offs[i + 1] - g_offs[i] + TILE - 1) / TILE;
            if (e < 0 && b < acc + tiles) { e = i; lt = b - acc; }
            acc += tiles;
        }
    }
    if (e < 0) return;
    const int base = g_offs[e] + lt * TILE;
    const int cnt = min(TILE, g_offs[e + 1] - base);

    int* sids = (int*)(sm + SM_SIDS);
    float* B0s = (float*)(sm + SM_B0);
    float* B1s = (float*)(sm + SM_B1);
    float* B2s = (float*)(sm + SM_B2);

    // ================= STAGING =================
    if (tid < TILE) {
        int n = g_order[base + min(tid, cnt - 1)];   // pad partial tiles with a valid row
        sids[tid] = n;
        float x[80];
        const float4* f4 = (const float4*)(features + (size_t)n * 32);
#pragma unroll
        for (int i = 0; i < 8; i++) {
            float4 f = f4[i];
            x[4 * i] = f.x; x[4 * i + 1] = f.y; x[4 * i + 2] = f.z; x[4 * i + 3] = f.w;
        }
        float p0 = positions[n * 3], p1 = positions[n * 3 + 1], p2 = positions[n * 3 + 2];
        x[32] = p0; x[33] = p1; x[34] = p2;
#pragma unroll
        for (int s = 0; s < 2; s++) {
            float sc = (float)(1 << s);
            x[35 + 3 * s] = __sinf(p0 * sc); x[36 + 3 * s] = __sinf(p1 * sc); x[37 + 3 * s] = __sinf(p2 * sc);
            x[41 + 3 * s] = __cosf(p0 * sc); x[42 + 3 * s] = __cosf(p1 * sc); x[43 + 3 * s] = __cosf(p2 * sc);
        }
        float q0 = viewdirs[n * 3], q1 = viewdirs[n * 3 + 1], q2 = viewdirs[n * 3 + 2];
        x[47] = q0; x[48] = q1; x[49] = q2;
#pragma unroll
        for (int s = 0; s < 4; s++) {
            float sc = (float)(1 << s);
            x[50 + 3 * s] = __sinf(q0 * sc); x[51 + 3 * s] = __sinf(q1 * sc); x[52 + 3 * s] = __sinf(q2 * sc);
            x[62 + 3 * s] = __cosf(q0 * sc); x[63 + 3 * s] = __cosf(q1 * sc); x[64 + 3 * s] = __cosf(q2 * sc);
        }
#pragma unroll
        for (int k = DIN; k < 80; k++) x[k] = 0.0f;
#pragma unroll
        for (int j = 0; j < 40; j++) {
            if (j < 32) {
                u32 off = SWZ((u32)(tid * 128 + j * 4));
                store_split(sm, SM_XH0 + off, SM_XL0 + off, x[2 * j], x[2 * j + 1]);
            } else {
                u32 off = (u32)(tid * 48 + (j - 32) * 4);
                store_split(sm, SM_XH1 + off, SM_XL1 + off, x[2 * j], x[2 * j + 1]);
            }
        }
    } else {
        int t2 = tid - TILE;
        const float* W0e = W0g + e * DIN * WID;
        for (int i = t2; i < 80 * 64; i += 128) {
            int k = i >> 6, c = i & 63;
            float v = (k < DIN) ? W0e[k * WID + c] : 0.0f;
            __nv_bfloat16 h = __float2bfloat16(v);
            __nv_bfloat16 l = __float2bfloat16(v - __bfloat162float(h));
            if (k < 64) {
                u32 off = SWZ((u32)(c * 128 + k * 2));
                *(__nv_bfloat16*)(sm + SM_W0H0 + off) = h;
                *(__nv_bfloat16*)(sm + SM_W0L0 + off) = l;
            } else {
                u32 off = (u32)(c * 48 + (k - 64) * 2);
                *(__nv_bfloat16*)(sm + SM_W0H1 + off) = h;
                *(__nv_bfloat16*)(sm + SM_W0L1 + off) = l;
            }
        }
        const float* W1e = W1g + e * WID * WID;
        for (int i = t2; i < 64 * 64; i += 128) {
            int k = i >> 6, c = i & 63;
            float v = W1e[k * WID + c];
            __nv_bfloat16 h = __float2bfloat16(v);
            __nv_bfloat16 l = __float2bfloat16(v - __bfloat162float(h));
            u32 off = SWZ((u32)(c * 128 + k * 2));
            *(__nv_bfloat16*)(sm + SM_W1H + off) = h;
            *(__nv_bfloat16*)(sm + SM_W1L + off) = l;
        }
        const float* W2e = W2g + e * WID * DOUT;
        for (int i = t2; i < 64 * 32; i += 128) {
            int k = i >> 5, c = i & 31;
            float v = W2e[k * DOUT + c];
            __nv_bfloat16 h = __float2bfloat16(v);
            __nv_bfloat16 l = __float2bfloat16(v - __bfloat162float(h));
            u32 off = SWZ((u32)(c * 128 + k * 2));
            *(__nv_bfloat16*)(sm + SM_W2H + off) = h;
            *(__nv_bfloat16*)(sm + SM_W2L + off) = l;
        }
        if (t2 < WID) { B0s[t2] = b0g[e * WID + t2]; B1s[t2] = b1g[e * WID + t2]; }
        if (t2 >= WID && t2 < WID + DOUT) B2s[t2 - WID] = b2g[e * DOUT + t2 - WID];
    }
    __syncthreads();

    // fragment lane coordinates
    const int wm = wid >> 1, wn = wid & 1;
    const int amat = lane >> 3, amr = lane & 7;
    const int arow_off = ((amat & 1) << 3) + amr;   // row within 16-row tile
    const int akoff = amat >> 1;                    // 16B k sub-chunk
    const int bmr = lane & 7, bmat = (lane >> 3) & 1;

    float C[2][4][4];

    // ================= LAYER 0 (K=80, N=64) =================
#pragma unroll
    for (int mt = 0; mt < 2; mt++)
#pragma unroll
        for (int nt = 0; nt < 4; nt++)
#pragma unroll
            for (int q = 0; q < 4; q++) C[mt][nt][q] = 0.0f;

#pragma unroll
    for (int mt = 0; mt < 2; mt++) {
        int arow = wm * 32 + mt * 16 + arow_off;
        u32 arb = (u32)(arow * 128);
        int ar7 = arow & 7;
        u32 ah[5][4], al[5][4];
#pragma unroll
        for (int kt = 0; kt < 4; kt++) {
            u32 off = arb + (u32)(((2 * kt + akoff) ^ ar7) << 4);
            ldmA(ah[kt], smb + SM_XH0 + off);
            ldmA(al[kt], smb + SM_XL0 + off);
        }
        {
            u32 off = (u32)(arow * 48 + (akoff << 4));
            ldmA(ah[4], smb + SM_XH1 + off);
            ldmA(al[4], smb + SM_XL1 + off);
        }
#pragma unroll
        for (int nt = 0; nt < 4; nt++) {
            int bn = wn * 32 + nt * 8 + bmr;
            u32 bnb = (u32)(bn * 128);
            int bn7 = bn & 7;
            u32 bh[5][2], bl[5][2];
#pragma unroll
            for (int kt = 0; kt < 4; kt++) {
                u32 off = bnb + (u32)(((2 * kt + bmat) ^ bn7) << 4);
                ldmB(bh[kt], smb + SM_W0H0 + off);
                ldmB(bl[kt], smb + SM_W0L0 + off);
            }
            {
                u32 off = (u32)(bn * 48 + (bmat << 4));
                ldmB(bh[4], smb + SM_W0H1 + off);
                ldmB(bl[4], smb + SM_W0L1 + off);
            }
#pragma unroll
            for (int kt = 0; kt < 5; kt++) {
                mma16816(C[mt][nt], ah[kt], bh[kt]);
                mma16816(C[mt][nt], ah[kt], bl[kt]);
                mma16816(C[mt][nt], al[kt], bh[kt]);
            }
        }
    }
    __syncthreads();   // all warps done reading X before H overwrites panel0

    // epilogue L0: bias+relu, split, write H into XH0/XL0
#pragma unroll
    for (int mt = 0; mt < 2; mt++)
#pragma unroll
        for (int nt = 0; nt < 4; nt++) {
            int row0 = wm * 32 + mt * 16 + (lane >> 2);
            int j0 = wn * 32 + nt * 8 + (lane & 3) * 2;
            float v0 = fmaxf(C[mt][nt][0] + B0s[j0], 0.0f);
            float v1 = fmaxf(C[mt][nt][1] + B0s[j0 + 1], 0.0f);
            float v2 = fmaxf(C[mt][nt][2] + B0s[j0], 0.0f);
            float v3 = fmaxf(C[mt][nt][3] + B0s[j0 + 1], 0.0f);
            u32 oa = SWZ((u32)(row0 * 128 + j0 * 2));
            u32 ob = SWZ((u32)((row0 + 8) * 128 + j0 * 2));
            store_split(sm, SM_XH0 + oa, SM_XL0 + oa, v0, v1);
            store_split(sm, SM_XH0 + ob, SM_XL0 + ob, v2, v3);
        }
    __syncthreads();

    // ================= LAYER 1 (K=64, N=64) =================
#pragma unroll
    for (int mt = 0; mt < 2; mt++)
#pragma unroll
        for (int nt = 0; nt < 4; nt++)
#pragma unroll
            for (int q = 0; q < 4; q++) C[mt][nt][q] = 0.0f;

#pragma unroll
    for (int mt = 0; mt < 2; mt++) {
        int arow = wm * 32 + mt * 16 + arow_off;
        u32 arb = (u32)(arow * 128);
        int ar7 = arow & 7;
        u32 ah[4][4], al[4][4];
#pragma unroll
        for (int kt = 0; kt < 4; kt++) {
            u32 off = arb + (u32)(((2 * kt + akoff) ^ ar7) << 4);
            ldmA(ah[kt], smb + SM_XH0 + off);
            ldmA(al[kt], smb + SM_XL0 + off);
        }
#pragma unroll
        for (int nt = 0; nt < 4; nt++) {
            int bn = wn * 32 + nt * 8 + bmr;
            u32 bnb = (u32)(bn * 128);
            int bn7 = bn & 7;
            u32 bh[4][2], bl[4][2];
#pragma unroll
            for (int kt = 0; kt < 4; kt++) {
                u32 off = bnb + (u32)(((2 * kt + bmat) ^ bn7) << 4);
                ldmB(bh[kt], smb + SM_W1H + off);
                ldmB(bl[kt], smb + SM_W1L + off);
            }
#pragma unroll
            for (int kt = 0; kt < 4; kt++) {
                mma16816(C[mt][nt], ah[kt], bh[kt]);
                mma16816(C[mt][nt], ah[kt], bl[kt]);
                mma16816(C[mt][nt], al[kt], bh[kt]);
            }
        }
    }
    __syncthreads();   // all warps done reading W1 region before G overwrites it

    // epilogue L1: bias+relu, split, write G (overlays W0/W1 region)
#pragma unroll
    for (int mt = 0; mt < 2; mt++)
#pragma unroll
        for (int nt = 0; nt < 4; nt++) {
            int row0 = wm * 32 + mt * 16 + (lane >> 2);
            int j0 = wn * 32 + nt * 8 + (lane & 3) * 2;
            float v0 = fmaxf(C[mt][nt][0] + B1s[j0], 0.0f);
            float v1 = fmaxf(C[mt][nt][1] + B1s[j0 + 1], 0.0f);
            float v2 = fmaxf(C[mt][nt][2] + B1s[j0], 0.0f);
            float v3 = fmaxf(C[mt][nt][3] + B1s[j0 + 1], 0.0f);
            u32 oa = SWZ((u32)(row0 * 128 + j0 * 2));
            u32 ob = SWZ((u32)((row0 + 8) * 128 + j0 * 2));
            store_split(sm, SM_GH + oa, SM_GL + oa, v0, v1);
            store_split(sm, SM_GH + ob, SM_GL + ob, v2, v3);
        }
    __syncthreads();

    // ================= LAYER 2 (K=64, N=32) =================
#pragma unroll
    for (int mt = 0; mt < 2; mt++)
#pragma unroll
        for (int nt = 0; nt < 2; nt++)
#pragma unroll
            for (int q = 0; q < 4; q++) C[mt][nt][q] = 0.0f;

#pragma unroll
    for (int mt = 0; mt < 2; mt++) {
        int arow = wm * 32 + mt * 16 + arow_off;
        u32 arb = (u32)(arow * 128);
        int ar7 = arow & 7;
        u32 ah[4][4], al[4][4];
#pragma unroll
        for (int kt = 0; kt < 4; kt++) {
            u32 off = arb + (u32)(((2 * kt + akoff) ^ ar7) << 4);
            ldmA(ah[kt], smb + SM_GH + off);
            ldmA(al[kt], smb + SM_GL + off);
        }
#pragma unroll
        for (int nt = 0; nt < 2; nt++) {
            int bn = wn * 16 + nt * 8 + bmr;
            u32 bnb = (u32)(bn * 128);
            int bn7 = bn & 7;
            u32 bh[4][2], bl[4][2];
#pragma unroll
            for (int kt = 0; kt < 4; kt++) {
                u32 off = bnb + (u32)(((2 * kt + bmat) ^ bn7) << 4);
                ldmB(bh[kt], smb + SM_W2H + off);
                ldmB(bl[kt], smb + SM_W2L + off);
            }
#pragma unroll
            for (int kt = 0; kt < 4; kt++) {
                mma16816(C[mt][nt], ah[kt], bh[kt]);
                mma16816(C[mt][nt], ah[kt], bl[kt]);
                mma16816(C[mt][nt], al[kt], bh[kt]);
            }
        }
    }

    // final epilogue: bias, scatter fp32 rows to gmem
#pragma unroll
    for (int mt = 0; mt < 2; mt++)
#pragma unroll
        for (int nt = 0; nt < 2; nt++) {
            int row0 = wm * 32 + mt * 16 + (lane >> 2);
            int j0 = wn * 16 + nt * 8 + (lane & 3) * 2;
            float o0 = C[mt][nt][0] + B2s[j0];
            float o1 = C[mt][nt][1] + B2s[j0 + 1];
            float o2 = C[mt][nt][2] + B2s[j0];
            float o3 = C[mt][nt][3] + B2s[j0 + 1];
            if (row0 < cnt)
                *(float2*)(out + (size_t)sids[row0] * DOUT + j0) = make_float2(o0, o1);
            if (row0 + 8 < cnt)
                *(float2*)(out + (size_t)sids[row0 + 8] * DOUT + j0) = make_float2(o2, o3);
        }
}

// ---------------- launch ----------------
extern "C" void kernel_launch(void* const* d_in, const int* in_sizes, int n_in,
                              void* d_out, int out_size) {
    (void)in_sizes; (void)n_in; (void)out_size;
    const int*   idxs      = (const int*)d_in[0];
    const float* positions = (const float*)d_in[1];
    const float* viewdirs  = (const float*)d_in[2];
    const float* features  = (const float*)d_in[3];
    const float* W0 = (const float*)d_in[4];
    const float* b0 = (const float*)d_in[5];
    const float* W1 = (const float*)d_in[6];
    const float* b1 = (const float*)d_in[7];
    const float* W2 = (const float*)d_in[8];
    const float* b2 = (const float*)d_in[9];
    float* out = (float*)d_out;

    cudaFuncSetAttribute(k_mlp, cudaFuncAttributeMaxDynamicSharedMemorySize, SMEM_BYTES);

    k_hist<<<NSCAT, 256>>>(idxs);
    k_scan<<<1, 1>>>();
    k_scatter<<<NSCAT, 256>>>(idxs);
    k_mlp<<<MAXTILES, NT, SMEM_BYTES>>>(positions, viewdirs, features,
                                        W0, b0, W1, b1, W2, b2, out);
}